// round 1
// baseline (speedup 1.0000x reference)
#include <cuda_runtime.h>
#include <math.h>

#define PI_D 3.14159265358979323846

#define NLAT 256
#define NLON 256
#define LMAX 128
#define MM   128              // effective mmax (P row m=128 is identically zero)
#define CIN  32
#define COUT 32
#define BATCH 8
#define BC   (BATCH*CIN)      // 256
#define BO   (BATCH*COUT)     // 256
#define J2   (2*MM)           // 256 interleaved (m,ri) columns
#define ROWS_X (BC*NLAT)      // 65536
#define ROWS_L (BC*LMAX)      // 32768
#define XSTRIDE (2*LMAX*129)  // 33024  (weight coeff stride uses MMAX=129)

// ---------------- scratch (device globals; no runtime allocation) ----------------
__device__ float g_wq[NLAT];
__device__ float g_Bdft[NLON*J2];          // [n][j]   j=2m+ri : fwd DFT basis (scaled 2pi/256)
__device__ float g_Binv[J2*NLON];          // [j][n]   inverse real-DFT basis (with c_m)
__device__ float g_PCTW[MM*NLAT*LMAX];     // [m][k][l]  P*wq   (zeros where l<m, never written)
__device__ float g_PCT [MM*LMAX*NLAT];     // [m][l][k]  P
__device__ float g_F   [J2*ROWS_X];        // [j][bc*256+k]   FFT output (re/im interleaved in j)
__device__ float g_CF  [J2*ROWS_L];        // [j][bc*128+l]   fwd Legendre output
__device__ float g_spec[ROWS_L*J2];        // [bc*128+l][j]   spec in weight-x order
__device__ float g_ospec[ROWS_L*J2];       // [bo*128+l][j]
__device__ float g_T   [J2*ROWS_L];        // [j][bo*128+l]
__device__ float g_G   [J2*ROWS_X];        // [j][bo*256+k]   inverse-Legendre output (A^T for inv DFT)

// ---------------- table init ----------------
__global__ void k_init_w() {
    int j = threadIdx.x;
    double t = PI_D * j / 255.0;
    double S = 0.0;
    for (int k = 1; k <= 127; k++)
        S += 2.0 / (4.0 * (double)k * k - 1.0) * cos(2.0 * t * k);
    double c = (j == 0 || j == 255) ? 1.0 : 2.0;
    g_wq[j] = (float)(c / 255.0 * (1.0 - S));
}

__global__ void k_init_P() {
    int m = blockIdx.x;        // 0..127
    int k = threadIdx.x;       // 0..255
    double t  = PI_D * k / 255.0;
    double ct = cos(t), st = sin(t);
    double w  = (double)g_wq[k];
    double pmm = 1.0 / sqrt(4.0 * PI_D);
    for (int j = 1; j <= m; j++)
        pmm *= -sqrt((2.0 * j + 1.0) / (2.0 * j)) * st;
    size_t wbase = ((size_t)m * NLAT + k) * LMAX;
    size_t pbase = (size_t)m * LMAX * NLAT + k;
    double pl0 = pmm;
    g_PCTW[wbase + m] = (float)(pl0 * w);
    g_PCT [pbase + (size_t)m * NLAT] = (float)pl0;
    if (m + 1 < LMAX) {
        double pl1 = sqrt(2.0 * m + 3.0) * ct * pl0;
        g_PCTW[wbase + m + 1] = (float)(pl1 * w);
        g_PCT [pbase + (size_t)(m + 1) * NLAT] = (float)pl1;
        for (int l = m + 2; l < LMAX; l++) {
            double dl = (double)l, dm = (double)m;
            double a = sqrt((4.0 * dl * dl - 1.0) / (dl * dl - dm * dm));
            double b = sqrt(((dl - 1.0) * (dl - 1.0) - dm * dm) /
                            (4.0 * (dl - 1.0) * (dl - 1.0) - 1.0));
            double p = a * (ct * pl1 - b * pl0);
            g_PCTW[wbase + l] = (float)(p * w);
            g_PCT [pbase + (size_t)l * NLAT] = (float)p;
            pl0 = pl1; pl1 = p;
        }
    }
}

__global__ void k_init_dft() {
    int idx = blockIdx.x * 256 + threadIdx.x;   // 65536
    int n = idx / J2, j = idx % J2;
    int m = j >> 1, ri = j & 1;
    double ang = 2.0 * PI_D * (double)(m * n) / 256.0;
    double s = 2.0 * PI_D / 256.0;
    g_Bdft[idx] = (float)(ri == 0 ? s * cos(ang) : -s * sin(ang));
    double cm = (m == 0) ? 1.0 : 2.0;
    g_Binv[(size_t)j * NLON + n] = (float)(ri == 0 ? cm * cos(ang) : -cm * sin(ang));
}

// ---------------- shared GEMM machinery (BM=BN=64, BK=16, 256 thr, 4x4/thread) ----
#define TBM 64
#define TBN 64
#define TBK 16
#define LDA_S (TBM + 4)

__device__ __forceinline__ void gemm_rm_loop(const float* __restrict__ A, int lda,
        const float* __restrict__ B, int ldb, int kbeg, int kend,
        float (&acc)[4][4], float* As, float* Bs)
{
    int tid = threadIdx.x;
    int arow = tid >> 2, ac4 = (tid & 3) << 2;
    int brow = tid >> 4, bc4 = (tid & 15) << 2;
    int tx = tid & 15, ty = tid >> 4;
    for (int kt = kbeg; kt < kend; kt += TBK) {
        float4 av = *(const float4*)(A + (size_t)arow * lda + kt + ac4);
        float4 bv = *(const float4*)(B + (size_t)(kt + brow) * ldb + bc4);
        __syncthreads();
        As[(ac4 + 0) * LDA_S + arow] = av.x;
        As[(ac4 + 1) * LDA_S + arow] = av.y;
        As[(ac4 + 2) * LDA_S + arow] = av.z;
        As[(ac4 + 3) * LDA_S + arow] = av.w;
        *(float4*)(Bs + brow * TBN + bc4) = bv;
        __syncthreads();
#pragma unroll
        for (int kk = 0; kk < TBK; kk++) {
            float4 af = *(const float4*)(As + kk * LDA_S + (ty << 2));
            float4 bf = *(const float4*)(Bs + kk * TBN + (tx << 2));
            float ar[4] = {af.x, af.y, af.z, af.w};
            float br[4] = {bf.x, bf.y, bf.z, bf.w};
#pragma unroll
            for (int i = 0; i < 4; i++)
#pragma unroll
                for (int jj = 0; jj < 4; jj++)
                    acc[i][jj] += ar[i] * br[jj];
        }
    }
}

// A given transposed: AT[k][row], ldat = total rows
__device__ __forceinline__ void gemm_tm_loop(const float* __restrict__ AT, int ldat,
        const float* __restrict__ B, int ldb, int kbeg, int kend,
        float (&acc)[4][4], float* As, float* Bs)
{
    int tid = threadIdx.x;
    int krow = tid >> 4, rc4 = (tid & 15) << 2;
    int tx = tid & 15, ty = tid >> 4;
    for (int kt = kbeg; kt < kend; kt += TBK) {
        float4 av = *(const float4*)(AT + (size_t)(kt + krow) * ldat + rc4);
        float4 bv = *(const float4*)(B + (size_t)(kt + krow) * ldb + rc4);
        __syncthreads();
        *(float4*)(As + krow * LDA_S + rc4) = av;
        *(float4*)(Bs + krow * TBN + rc4) = bv;
        __syncthreads();
#pragma unroll
        for (int kk = 0; kk < TBK; kk++) {
            float4 af = *(const float4*)(As + kk * LDA_S + (ty << 2));
            float4 bf = *(const float4*)(Bs + kk * TBN + (tx << 2));
            float ar[4] = {af.x, af.y, af.z, af.w};
            float br[4] = {bf.x, bf.y, bf.z, bf.w};
#pragma unroll
            for (int i = 0; i < 4; i++)
#pragma unroll
                for (int jj = 0; jj < 4; jj++)
                    acc[i][jj] += ar[i] * br[jj];
        }
    }
}

// ---------------- stage kernels ----------------
// fwd DFT: C[row=(b,c,k)][j] = sum_n x[row][n]*Bdft[n][j]; write transposed to g_F[j][row]
__global__ __launch_bounds__(256) void k_fft_fwd(const float* __restrict__ X) {
    __shared__ float As[TBK * LDA_S];
    __shared__ float Bs[TBK * TBN];
    __shared__ float Cs[TBN * (TBM + 1)];
    int tid = threadIdx.x;
    int row0 = blockIdx.x * TBM, col0 = blockIdx.y * TBN;
    int tx = tid & 15, ty = tid >> 4;
    float acc[4][4] = {};
    gemm_rm_loop(X + (size_t)row0 * NLON, NLON, g_Bdft + col0, J2, 0, NLON, acc, As, Bs);
    __syncthreads();
#pragma unroll
    for (int i = 0; i < 4; i++)
#pragma unroll
        for (int jj = 0; jj < 4; jj++)
            Cs[(tx * 4 + jj) * (TBM + 1) + ty * 4 + i] = acc[i][jj];
    __syncthreads();
    for (int it = 0; it < 16; it++) {
        int flat = it * 256 + tid;
        int cl = flat >> 6, rl = flat & 63;
        g_F[(size_t)(col0 + cl) * ROWS_X + row0 + rl] = Cs[cl * (TBM + 1) + rl];
    }
}

// fwd Legendre (batched over m): C[sr][l] = sum_k F[2m..][sr][k]*PCTW[m][k][l]
__global__ __launch_bounds__(256) void k_leg_fwd() {
    int m = blockIdx.z;
    int l0 = blockIdx.y * TBN;
    if (l0 + TBN - 1 < m) return;              // triangular: l<m is zero
    int sr0 = blockIdx.x * TBM;
    __shared__ float As[TBK * LDA_S];
    __shared__ float Bs[TBK * TBN];
    int tid = threadIdx.x, tx = tid & 15, ty = tid >> 4;
    float acc[4][4] = {};
    const float* A = g_F + (size_t)(2 * m) * ROWS_X + (size_t)sr0 * NLAT;
    const float* B = g_PCTW + (size_t)m * NLAT * LMAX + l0;
    gemm_rm_loop(A, NLAT, B, LMAX, 0, NLAT, acc, As, Bs);
    float* Cp = g_CF + (size_t)(2 * m) * ROWS_L + (size_t)sr0 * LMAX + l0;
#pragma unroll
    for (int i = 0; i < 4; i++)
        *(float4*)(Cp + (size_t)(ty * 4 + i) * LMAX + tx * 4) =
            make_float4(acc[i][0], acc[i][1], acc[i][2], acc[i][3]);
}

// transpose g_CF [256][32768] -> g_spec [32768][256]
__global__ void k_t1() {
    __shared__ float t[32][33];
    int c0 = blockIdx.x * 32, r0 = blockIdx.y * 32;   // src rows=j (256), cols=32768
    for (int i = threadIdx.y; i < 32; i += 8)
        t[i][threadIdx.x] = g_CF[(size_t)(r0 + i) * ROWS_L + c0 + threadIdx.x];
    __syncthreads();
    for (int i = threadIdx.y; i < 32; i += 8)
        g_spec[(size_t)(c0 + i) * J2 + r0 + threadIdx.x] = t[threadIdx.x][i];
}

// per-coefficient channel mix: out[b,o,x] = sum_i spec[b,i,x]*w[i,o,x]
__global__ __launch_bounds__(256) void k_mix(const float* __restrict__ w) {
    int l = blockIdx.y;
    int jt = blockIdx.x;
    if (jt * 16 > l) return;                   // whole tile has m>l -> zero
    int j0 = jt * 32;
    __shared__ float ws[32 * 33];
    __shared__ float ss[8 * 32];
    int tid = threadIdx.x;
    int o = tid >> 3, jg = tid & 7;
    float acc[4][8] = {};
    for (int i = 0; i < CIN; i++) {
        __syncthreads();
        for (int t = tid; t < 1024; t += 256) {
            int oo = t >> 5, jj = t & 31;
            ws[oo * 33 + jj] = w[(size_t)(i * COUT + oo) * XSTRIDE + l * 258 + j0 + jj];
        }
        { int b = tid >> 5, jj = tid & 31;
          ss[b * 32 + jj] = g_spec[((size_t)(b * CIN + i) * LMAX + l) * J2 + j0 + jj]; }
        __syncthreads();
#pragma unroll
        for (int q = 0; q < 4; q++) {
            float wv = ws[o * 33 + jg + 8 * q];
#pragma unroll
            for (int b = 0; b < 8; b++)
                acc[q][b] += ss[b * 32 + jg + 8 * q] * wv;
        }
    }
#pragma unroll
    for (int q = 0; q < 4; q++)
#pragma unroll
        for (int b = 0; b < 8; b++)
            g_ospec[((size_t)(b * COUT + o) * LMAX + l) * J2 + j0 + jg + 8 * q] = acc[q][b];
}

// transpose g_ospec [32768][256] -> g_T [256][32768]
__global__ void k_t2() {
    __shared__ float t[32][33];
    int c0 = blockIdx.x * 32, r0 = blockIdx.y * 32;   // src rows=32768, cols=j (256)
    for (int i = threadIdx.y; i < 32; i += 8)
        t[i][threadIdx.x] = g_ospec[(size_t)(r0 + i) * J2 + c0 + threadIdx.x];
    __syncthreads();
    for (int i = threadIdx.y; i < 32; i += 8)
        g_T[(size_t)(c0 + i) * ROWS_L + r0 + threadIdx.x] = t[threadIdx.x][i];
}

// inv Legendre (batched over m): C[sr][k] = sum_l T[2m..][sr][l]*PCT[m][l][k]
__global__ __launch_bounds__(256) void k_leg_inv() {
    int m = blockIdx.z;
    int sr0 = blockIdx.x * TBM;
    int k0 = blockIdx.y * TBN;
    __shared__ float As[TBK * LDA_S];
    __shared__ float Bs[TBK * TBN];
    int tid = threadIdx.x, tx = tid & 15, ty = tid >> 4;
    float acc[4][4] = {};
    const float* A = g_T + (size_t)(2 * m) * ROWS_L + (size_t)sr0 * LMAX;
    const float* B = g_PCT + (size_t)m * LMAX * NLAT + k0;
    int kbeg = m & ~(TBK - 1);                 // l<m contributes zero
    gemm_rm_loop(A, LMAX, B, NLAT, kbeg, LMAX, acc, As, Bs);
    float* Cp = g_G + (size_t)(2 * m) * ROWS_X + (size_t)sr0 * NLAT + k0;
#pragma unroll
    for (int i = 0; i < 4; i++)
        *(float4*)(Cp + (size_t)(ty * 4 + i) * NLAT + tx * 4) =
            make_float4(acc[i][0], acc[i][1], acc[i][2], acc[i][3]);
}

// inv DFT: y[row=(b,o,k)][n] = sum_j G[j][row]*Binv[j][n]
__global__ __launch_bounds__(256) void k_fft_inv(float* __restrict__ Y) {
    __shared__ float As[TBK * LDA_S];
    __shared__ float Bs[TBK * TBN];
    int tid = threadIdx.x, tx = tid & 15, ty = tid >> 4;
    int row0 = blockIdx.x * TBM, n0 = blockIdx.y * TBN;
    float acc[4][4] = {};
    gemm_tm_loop(g_G + row0, ROWS_X, g_Binv + n0, NLON, 0, J2, acc, As, Bs);
    float* Cp = Y + (size_t)row0 * NLON + n0;
#pragma unroll
    for (int i = 0; i < 4; i++)
        *(float4*)(Cp + (size_t)(ty * 4 + i) * NLON + tx * 4) =
            make_float4(acc[i][0], acc[i][1], acc[i][2], acc[i][3]);
}

// ---------------- launcher ----------------
extern "C" void kernel_launch(void* const* d_in, const int* in_sizes, int n_in,
                              void* d_out, int out_size) {
    const float* x = (const float*)d_in[0];
    const float* w = (const float*)d_in[1];
    if (n_in >= 2 && in_sizes[0] != BATCH * CIN * NLAT * NLON) {  // defensive order check
        const float* t = x; x = w; w = t;
    }
    float* y = (float*)d_out;

    k_init_w  <<<1, 256>>>();
    k_init_P  <<<128, 256>>>();
    k_init_dft<<<256, 256>>>();

    k_fft_fwd <<<dim3(ROWS_X / TBM, J2 / TBN), 256>>>(x);
    k_leg_fwd <<<dim3((2 * BC) / TBM, LMAX / TBN, MM), 256>>>();
    k_t1      <<<dim3(ROWS_L / 32, J2 / 32), dim3(32, 8)>>>();
    k_mix     <<<dim3(8, LMAX), 256>>>(w);
    k_t2      <<<dim3(J2 / 32, ROWS_L / 32), dim3(32, 8)>>>();
    k_leg_inv <<<dim3((2 * BO) / TBM, NLAT / TBN, MM), 256>>>();
    k_fft_inv <<<dim3(ROWS_X / TBM, NLON / TBN), 256>>>(y);
}

// round 6
// speedup vs baseline: 2.4399x; 2.4399x over previous
#include <cuda_runtime.h>
#include <cuda_bf16.h>
#include <math.h>

#define PI_D 3.14159265358979323846

#define NLAT 256
#define NLON 256
#define LMAX 128
#define MM   128
#define CIN  32
#define COUT 32
#define BATCH 8
#define BC   (BATCH*CIN)      // 256
#define J2   (2*MM)           // 256
#define ROWS_X (BC*NLAT)      // 65536
#define ROWS_L (BC*LMAX)      // 32768
#define XSTRIDE (2*LMAX*129)  // 33024

// ---------------- tables (bf16 hi/lo, K-major as MMA B operands) ----------------
__device__ float g_wq[NLAT];
__device__ __nv_bfloat16 g_Dh[256*256], g_Dl[256*256];         // fwd DFT  B[j][n]
__device__ __nv_bfloat16 g_Ih[256*256], g_Il[256*256];         // inv DFT  B[n][j]
__device__ __nv_bfloat16 g_Wh[128*128*256], g_Wl[128*128*256]; // [m][l][k] = P*wq (l<m stays 0)
__device__ __nv_bfloat16 g_Ph[128*256*128], g_Pl[128*256*128]; // [m][k][l] = P

// ---------------- activations ----------------
__device__ float g_F   [256*65536];   // [j][bc*256+k]
__device__ float g_CF  [256*32768];   // [j][bc*128+l]
__device__ float g_spec[32768*256];   // [(b,i)*128+l][j]
__device__ float g_ospec[32768*256];  // [(b,o)*128+l][j]  (l<m tiles stay 0 from BSS)
__device__ float g_T   [256*32768];   // [j][bo*128+l]
__device__ float g_G   [256*65536];   // stage1 temp [row][j]  /  stage6 out [j][row]
__device__ float g_G2  [65536*256];   // [bo*256+k][j]

// ---------------- helpers ----------------
__device__ __forceinline__ unsigned smem_u32(const void* p) {
    unsigned a;
    asm("{ .reg .u64 t; cvta.to.shared.u64 t, %1; cvt.u32.u64 %0, t; }" : "=r"(a) : "l"(p));
    return a;
}
__device__ __forceinline__ unsigned pk(__nv_bfloat16 a, __nv_bfloat16 b) {
    unsigned short ua = *reinterpret_cast<unsigned short*>(&a);
    unsigned short ub = *reinterpret_cast<unsigned short*>(&b);
    return (unsigned)ua | ((unsigned)ub << 16);
}
__device__ __forceinline__ void bf16split(float v, __nv_bfloat16& h, __nv_bfloat16& l) {
    h = __float2bfloat16(v);
    l = __float2bfloat16(v - __bfloat162float(h));
}
#define LDSM4(r0, r1, r2, r3, ad)                                                   \
    asm volatile("ldmatrix.sync.aligned.m8n8.x4.shared.b16 {%0,%1,%2,%3}, [%4];"    \
                 : "=r"(r0), "=r"(r1), "=r"(r2), "=r"(r3) : "r"(ad))
#define MMA16816(c, a, b0, b1)                                                      \
    asm volatile("mma.sync.aligned.m16n8k16.row.col.f32.bf16.bf16.f32 "             \
                 "{%0,%1,%2,%3},{%4,%5,%6,%7},{%8,%9},{%0,%1,%2,%3};"               \
                 : "+f"((c)[0]), "+f"((c)[1]), "+f"((c)[2]), "+f"((c)[3])           \
                 : "r"((a)[0]), "r"((a)[1]), "r"((a)[2]), "r"((a)[3]),              \
                   "r"(b0), "r"(b1))

// ---------------- table init (fp32, exact integer angle reduction) ----------------
__global__ void k_init_w() {
    int j = threadIdx.x;
    float S = 0.0f;
    for (int k = 1; k <= 127; k++) {
        int r = (j * k) % 255;
        S += 2.0f / (4.0f * k * k - 1.0f) * cosf(2.0f * (float)PI_D * r / 255.0f);
    }
    float c = (j == 0 || j == 255) ? 1.0f : 2.0f;
    g_wq[j] = c / 255.0f * (1.0f - S);
}

__global__ void k_init_P() {
    int m = blockIdx.x;        // 0..127
    int k = threadIdx.x;       // 0..255
    float t  = (float)(PI_D * k / 255.0);
    float ct = cosf(t), st = sinf(t);
    float w  = g_wq[k];
    float pmm = 0.28209479177387814f;                 // 1/sqrt(4*pi)
    for (int j = 1; j <= m; j++)
        pmm *= -sqrtf((2.0f * j + 1.0f) / (2.0f * j)) * st;

    __nv_bfloat16 h, l;
    float pl0 = pmm;
    {   float pw = pl0 * w;
        bf16split(pw, h, l);
        g_Wh[((size_t)m * LMAX + m) * 256 + k] = h;  g_Wl[((size_t)m * LMAX + m) * 256 + k] = l;
        bf16split(pl0, h, l);
        g_Ph[((size_t)m * 256 + k) * LMAX + m] = h;  g_Pl[((size_t)m * 256 + k) * LMAX + m] = l; }
    if (m + 1 < LMAX) {
        float pl1 = sqrtf(2.0f * m + 3.0f) * ct * pmm;
        float pw = pl1 * w;
        bf16split(pw, h, l);
        g_Wh[((size_t)m * LMAX + m + 1) * 256 + k] = h;  g_Wl[((size_t)m * LMAX + m + 1) * 256 + k] = l;
        bf16split(pl1, h, l);
        g_Ph[((size_t)m * 256 + k) * LMAX + m + 1] = h;  g_Pl[((size_t)m * 256 + k) * LMAX + m + 1] = l;
        for (int ll = m + 2; ll < LMAX; ll++) {
            float dl = (float)ll, dm = (float)m;
            float a = sqrtf((4.0f * dl * dl - 1.0f) / (dl * dl - dm * dm));
            float b = sqrtf(((dl - 1.0f) * (dl - 1.0f) - dm * dm) /
                            (4.0f * (dl - 1.0f) * (dl - 1.0f) - 1.0f));
            float p = a * (ct * pl1 - b * pl0);
            float pw2 = p * w;
            bf16split(pw2, h, l);
            g_Wh[((size_t)m * LMAX + ll) * 256 + k] = h;  g_Wl[((size_t)m * LMAX + ll) * 256 + k] = l;
            bf16split(p, h, l);
            g_Ph[((size_t)m * 256 + k) * LMAX + ll] = h;  g_Pl[((size_t)m * 256 + k) * LMAX + ll] = l;
            pl0 = pl1; pl1 = p;
        }
    }
}

__global__ void k_init_dft() {
    int a = blockIdx.x, b = threadIdx.x;   // both 0..255
    __nv_bfloat16 h, l;
    {   // g_D[j=a][n=b]
        int m = a >> 1, ri = a & 1;
        float th = 2.0f * (float)PI_D * (float)((m * b) & 255) / 256.0f;
        float s = 2.0f * (float)PI_D / 256.0f;
        float v = ri ? -s * sinf(th) : s * cosf(th);
        bf16split(v, h, l);
        g_Dh[a * 256 + b] = h;  g_Dl[a * 256 + b] = l;
    }
    {   // g_I[n=a][j=b]
        int m = b >> 1, ri = b & 1;
        float th = 2.0f * (float)PI_D * (float)((m * a) & 255) / 256.0f;
        float cm = (m == 0) ? 1.0f : 2.0f;
        float v = ri ? -cm * sinf(th) : cm * cosf(th);
        bf16split(v, h, l);
        g_Ih[a * 256 + b] = h;  g_Il[a * 256 + b] = l;
    }
}

// ---------------- warp-MMA split-bf16 GEMM --------------------------------------
// C[128x128 tile] = A(fp32 [rows x K], row-major) * B^T, B given [N][K] K-major bf16 hi/lo.
// 3-term split: C = Ah*Bh + Ah*Bl + Al*Bh, fp32 accumulators.
#define RP 40   // smem row pitch in bf16 elems (80 bytes) -> conflict-free ldmatrix

__global__ void __launch_bounds__(256) k_gemm(
    const float* __restrict__ A, size_t sA, int lda,
    const __nv_bfloat16* __restrict__ Bh, const __nv_bfloat16* __restrict__ Bl, size_t sB,
    float* __restrict__ C, size_t sC, int ldc, int K, int tri)
{
    __shared__ __nv_bfloat16 sAh[128 * RP], sAl[128 * RP];
    __shared__ __nv_bfloat16 sBh[128 * RP], sBl[128 * RP];

    int tid = threadIdx.x, lane = tid & 31, wid = tid >> 5;
    int z = blockIdx.z;
    A  += sA * z;  Bh += sB * z;  Bl += sB * z;  C += sC * z;
    size_t row0 = (size_t)blockIdx.x * 128;
    int col0 = blockIdx.y * 128;
    int wm = wid & 3, wn = wid >> 2;       // warp tile: rows wm*32 (+32), cols wn*64 (+64)

    float acc[2][8][4] = {};

    // ldmatrix per-lane addressing
    int a_row = (lane & 7) + ((lane >> 3) & 1) * 8;
    int a_ko  = (lane >> 4) * 8;
    int b_row = (lane & 7) + ((lane >> 4) & 1) * 8;
    int b_ko  = ((lane >> 3) & 1) * 8;

    unsigned uAh = smem_u32(sAh), uAl = smem_u32(sAl);
    unsigned uBh = smem_u32(sBh), uBl = smem_u32(sBl);

    int kb = tri ? (z & ~31) : 0;

    for (int k0 = kb; k0 < K; k0 += 32) {
        // ---- global loads into regs
        float4 av[4];
        uint4  bhv[2], blv[2];
#pragma unroll
        for (int rp = 0; rp < 4; rp++) {
            int idx = rp * 256 + tid;
            int r = idx >> 3, kq = idx & 7;
            av[rp] = *(const float4*)(A + (row0 + r) * lda + k0 + kq * 4);
        }
#pragma unroll
        for (int rp = 0; rp < 2; rp++) {
            int idx = rp * 256 + tid;
            int r = idx >> 2, q = idx & 3;
            bhv[rp] = *(const uint4*)(Bh + (size_t)(col0 + r) * K + k0 + q * 8);
            blv[rp] = *(const uint4*)(Bl + (size_t)(col0 + r) * K + k0 + q * 8);
        }
        __syncthreads();   // previous iteration's compute done
        // ---- store to smem (A split to hi/lo)
#pragma unroll
        for (int rp = 0; rp < 4; rp++) {
            int idx = rp * 256 + tid;
            int r = idx >> 3, kq = idx & 7;
            __nv_bfloat16 h0, h1, h2, h3, l0, l1, l2, l3;
            bf16split(av[rp].x, h0, l0); bf16split(av[rp].y, h1, l1);
            bf16split(av[rp].z, h2, l2); bf16split(av[rp].w, h3, l3);
            uint2 hh; hh.x = pk(h0, h1); hh.y = pk(h2, h3);
            uint2 ll; ll.x = pk(l0, l1); ll.y = pk(l2, l3);
            *(uint2*)((char*)sAh + r * 80 + kq * 8) = hh;
            *(uint2*)((char*)sAl + r * 80 + kq * 8) = ll;
        }
#pragma unroll
        for (int rp = 0; rp < 2; rp++) {
            int idx = rp * 256 + tid;
            int r = idx >> 2, q = idx & 3;
            *(uint4*)((char*)sBh + r * 80 + q * 16) = bhv[rp];
            *(uint4*)((char*)sBl + r * 80 + q * 16) = blv[rp];
        }
        __syncthreads();
        // ---- compute: two k16 steps
#pragma unroll
        for (int s = 0; s < 2; s++) {
            unsigned ah[2][4], al[2][4];
#pragma unroll
            for (int mt = 0; mt < 2; mt++) {
                unsigned off = (unsigned)((wm * 32 + mt * 16 + a_row) * 80 + (s * 16 + a_ko) * 2);
                LDSM4(ah[mt][0], ah[mt][1], ah[mt][2], ah[mt][3], uAh + off);
                LDSM4(al[mt][0], al[mt][1], al[mt][2], al[mt][3], uAl + off);
            }
#pragma unroll
            for (int nt = 0; nt < 4; nt++) {
                unsigned off = (unsigned)((wn * 64 + nt * 16 + b_row) * 80 + (s * 16 + b_ko) * 2);
                unsigned bh0, bh1, bh2, bh3, bl0, bl1, bl2, bl3;
                LDSM4(bh0, bh1, bh2, bh3, uBh + off);
                LDSM4(bl0, bl1, bl2, bl3, uBl + off);
#pragma unroll
                for (int mt = 0; mt < 2; mt++) {
                    MMA16816(acc[mt][2 * nt],     ah[mt], bh0, bh1);
                    MMA16816(acc[mt][2 * nt + 1], ah[mt], bh2, bh3);
                    MMA16816(acc[mt][2 * nt],     ah[mt], bl0, bl1);
                    MMA16816(acc[mt][2 * nt + 1], ah[mt], bl2, bl3);
                    MMA16816(acc[mt][2 * nt],     al[mt], bh0, bh1);
                    MMA16816(acc[mt][2 * nt + 1], al[mt], bh2, bh3);
                }
            }
        }
    }

    // ---- epilogue: row-major C
    int g = lane >> 2, tt = lane & 3;
#pragma unroll
    for (int mt = 0; mt < 2; mt++)
#pragma unroll
        for (int ntq = 0; ntq < 8; ntq++) {
            float* base = C + (row0 + wm * 32 + mt * 16 + g) * ldc
                            + col0 + wn * 64 + ntq * 8 + tt * 2;
            float2 v0; v0.x = acc[mt][ntq][0]; v0.y = acc[mt][ntq][1];
            float2 v1; v1.x = acc[mt][ntq][2]; v1.y = acc[mt][ntq][3];
            *(float2*)base = v0;
            *(float2*)(base + 8 * (size_t)ldc) = v1;
        }
}

// ---------------- transpose: src[R][C_] -> dst[C_][R] ----------------
__global__ void k_tr(const float* __restrict__ src, float* __restrict__ dst, int R, int C_) {
    __shared__ float t[32][33];
    int c0 = blockIdx.x * 32, r0 = blockIdx.y * 32;
    for (int i = threadIdx.y; i < 32; i += 8)
        t[i][threadIdx.x] = src[(size_t)(r0 + i) * C_ + c0 + threadIdx.x];
    __syncthreads();
    for (int i = threadIdx.y; i < 32; i += 8)
        dst[(size_t)(c0 + i) * R + r0 + threadIdx.x] = t[threadIdx.x][i];
}

// ---------------- per-coefficient channel mix (verified in R1) ----------------
__global__ __launch_bounds__(256) void k_mix(const float* __restrict__ w) {
    int l = blockIdx.y;
    int jt = blockIdx.x;
    if (jt * 16 > l) return;
    int j0 = jt * 32;
    __shared__ float ws[32 * 33];
    __shared__ float ss[8 * 32];
    int tid = threadIdx.x;
    int o = tid >> 3, jg = tid & 7;
    float acc[4][8] = {};
    for (int i = 0; i < CIN; i++) {
        __syncthreads();
        for (int t = tid; t < 1024; t += 256) {
            int oo = t >> 5, jj = t & 31;
            ws[oo * 33 + jj] = w[(size_t)(i * COUT + oo) * XSTRIDE + l * 258 + j0 + jj];
        }
        { int b = tid >> 5, jj = tid & 31;
          ss[b * 32 + jj] = g_spec[((size_t)(b * CIN + i) * LMAX + l) * J2 + j0 + jj]; }
        __syncthreads();
#pragma unroll
        for (int q = 0; q < 4; q++) {
            float wv = ws[o * 33 + jg + 8 * q];
#pragma unroll
            for (int b = 0; b < 8; b++)
                acc[q][b] += ss[b * 32 + jg + 8 * q] * wv;
        }
    }
#pragma unroll
    for (int q = 0; q < 4; q++)
#pragma unroll
        for (int b = 0; b < 8; b++)
            g_ospec[((size_t)(b * COUT + o) * LMAX + l) * J2 + j0 + jg + 8 * q] = acc[q][b];
}

// ---------------- launcher ----------------
extern "C" void kernel_launch(void* const* d_in, const int* in_sizes, int n_in,
                              void* d_out, int out_size) {
    const float* x = (const float*)d_in[0];
    const float* w = (const float*)d_in[1];
    if (n_in >= 2 && in_sizes[0] != BATCH * CIN * NLAT * NLON) {
        const float* t = x; x = w; w = t;
    }
    float* y = (float*)d_out;

    void *pDh, *pDl, *pIh, *pIl, *pWh, *pWl, *pPh, *pPl;
    void *pF, *pCF, *pT, *pG, *pG2, *pSpec, *pOspec;
    cudaGetSymbolAddress(&pDh, g_Dh);  cudaGetSymbolAddress(&pDl, g_Dl);
    cudaGetSymbolAddress(&pIh, g_Ih);  cudaGetSymbolAddress(&pIl, g_Il);
    cudaGetSymbolAddress(&pWh, g_Wh);  cudaGetSymbolAddress(&pWl, g_Wl);
    cudaGetSymbolAddress(&pPh, g_Ph);  cudaGetSymbolAddress(&pPl, g_Pl);
    cudaGetSymbolAddress(&pF, g_F);    cudaGetSymbolAddress(&pCF, g_CF);
    cudaGetSymbolAddress(&pT, g_T);    cudaGetSymbolAddress(&pG, g_G);
    cudaGetSymbolAddress(&pG2, g_G2);
    cudaGetSymbolAddress(&pSpec, g_spec); cudaGetSymbolAddress(&pOspec, g_ospec);

    k_init_w  <<<1, 256>>>();
    k_init_P  <<<128, 256>>>();
    k_init_dft<<<256, 256>>>();

    // 1) fwd DFT: tmp[(bc,k)][j] = x * D^T  (row-major into g_G)
    k_gemm<<<dim3(512, 2, 1), 256>>>(
        x, 0, NLON, (const __nv_bfloat16*)pDh, (const __nv_bfloat16*)pDl, 0,
        (float*)pG, 0, 256, 256, 0);
    // 1b) transpose -> g_F[j][(bc,k)]
    k_tr<<<dim3(8, 2048), dim3(32, 8)>>>((const float*)pG, (float*)pF, 65536, 256);

    // 2) fwd Legendre per m: g_CF[2m..][sr][l] = F_slab * W[m]^T
    k_gemm<<<dim3(4, 1, 128), 256>>>(
        (const float*)pF, (size_t)2 * ROWS_X, NLAT,
        (const __nv_bfloat16*)pWh, (const __nv_bfloat16*)pWl, (size_t)128 * 256,
        (float*)pCF, (size_t)2 * ROWS_L, LMAX, 256, 0);

    // 3) transpose -> spec layout for mix
    k_tr<<<dim3(1024, 8), dim3(32, 8)>>>((const float*)pCF, (float*)pSpec, 256, ROWS_L);

    // 4) channel mix
    k_mix<<<dim3(8, LMAX), 256>>>(w);

    // 5) transpose back
    k_tr<<<dim3(8, 1024), dim3(32, 8)>>>((const float*)pOspec, (float*)pT, ROWS_L, 256);

    // 6) inv Legendre per m (triangular K-skip): g_G[2m..][sr][k] = T_slab * P[m]^T
    k_gemm<<<dim3(4, 2, 128), 256>>>(
        (const float*)pT, (size_t)2 * ROWS_L, LMAX,
        (const __nv_bfloat16*)pPh, (const __nv_bfloat16*)pPl, (size_t)256 * 128,
        (float*)pG, (size_t)2 * ROWS_X, NLAT, 128, 1);

    // 7) transpose g_G[j][row] -> g_G2[row][j]
    k_tr<<<dim3(2048, 8), dim3(32, 8)>>>((const float*)pG, (float*)pG2, 256, ROWS_X);

    // 8) inv DFT: y[row][n] = G2 * I^T
    k_gemm<<<dim3(512, 2, 1), 256>>>(
        (const float*)pG2, 0, 256, (const __nv_bfloat16*)pIh, (const __nv_bfloat16*)pIl, 0,
        y, 0, 256, 256, 0);
}